// round 4
// baseline (speedup 1.0000x reference)
#include <cuda_runtime.h>
#include <float.h>

#define LD   128   // latent dims
#define NE   256   // num embeddings
#define MT   64    // rows per CTA
#define NCH  128   // embeddings per chunk (2 chunks)
#define NP   64    // column pairs per chunk
#define XS   132   // x smem stride (floats), float4-aligned
#define PS   64    // e pair-row stride (float2/ULL units)

__device__ float g_esq[NE];

// ---------------------------------------------------------------------------
// esq_kernel: esq[k] = sum_d e[k][d]^2
// ---------------------------------------------------------------------------
__global__ void esq_kernel(const float* __restrict__ emb) {
    int k = threadIdx.x;            // 0..255
    const float4* row = (const float4*)(emb + (size_t)k * LD);
    float s = 0.f;
#pragma unroll
    for (int q = 0; q < LD / 4; q++) {
        float4 v = row[q];
        s = fmaf(v.x, v.x, s);
        s = fmaf(v.y, v.y, s);
        s = fmaf(v.z, v.z, s);
        s = fmaf(v.w, v.w, s);
    }
    g_esq[k] = s;
}

// ---------------------------------------------------------------------------
// f32x2 helpers (packed fp32: 2 FMAs per instruction)
// ---------------------------------------------------------------------------
__device__ __forceinline__ unsigned long long pk2(float a, float b) {
    unsigned long long r;
    asm("mov.b64 %0, {%1, %2};" : "=l"(r) : "f"(a), "f"(b));
    return r;
}
__device__ __forceinline__ void upk2(unsigned long long v, float& a, float& b) {
    asm("mov.b64 {%0, %1}, %2;" : "=f"(a), "=f"(b) : "l"(v));
}
__device__ __forceinline__ unsigned long long fma2(unsigned long long a,
                                                   unsigned long long b,
                                                   unsigned long long c) {
    unsigned long long d;
    asm("fma.rn.f32x2 %0, %1, %2, %3;" : "=l"(d) : "l"(a), "l"(b), "l"(c));
    return d;
}

extern __shared__ float smem[];
// layout: sx[MT][XS] floats  |  se2[LD][PS] ULL (pair-transposed e chunk)

// ---------------------------------------------------------------------------
// Main kernel: fused GEMM + argmin + gather
// col_t = t&15 owns pairs p = col_t+16j (cols 2p, 2p+1); row_t = t>>4 owns
// rows row_t*4 + i. Thread tile 4 rows x 8 cols, FFMA2 packed over col pairs.
// ---------------------------------------------------------------------------
__global__ __launch_bounds__(256, 2)
void vq_kernel(const float* __restrict__ inp, const float* __restrict__ emb,
               float* __restrict__ out) {
    float* sx = smem;
    unsigned long long* se2 = (unsigned long long*)(smem + MT * XS);
    const int t     = threadIdx.x;
    const int col_t = t & 15;
    const int row_t = t >> 4;
    const int row0  = row_t * 4;
    const size_t base_row = (size_t)blockIdx.x * MT;

    // ---- load x tile [64][128] -> sx stride XS (coalesced LDG128/STS128) ----
    {
        const float4* gin = (const float4*)(inp + base_row * LD);
#pragma unroll
        for (int p = 0; p < 8; p++) {
            int fi  = t + p * 256;          // 0..2047
            int row = fi >> 5;              // /32 float4s per row
            int q   = fi & 31;
            float4 v = gin[fi];
            *(float4*)(sx + row * XS + q * 4) = v;
        }
    }

    float bestv[4];
    int   besti[4];
#pragma unroll
    for (int i = 0; i < 4; i++) { bestv[i] = FLT_MAX; besti[i] = 0; }

    for (int c = 0; c < 2; c++) {
        __syncthreads();   // previous chunk's readers done (also covers x STS)
        // ---- store e chunk pair-transposed: se2[k][p] = (e[2p][k], e[2p+1][k])
        {
            const float4* ge = (const float4*)(emb + (size_t)c * NCH * LD);
            int p   = t & 63;               // pair index
            int kq0 = (t >> 6) * 8;         // float4 index base within row
#pragma unroll
            for (int kb = 0; kb < 8; kb++) {
                float4 a = ge[(2 * p) * 32 + kq0 + kb];
                float4 b = ge[(2 * p + 1) * 32 + kq0 + kb];
                int k = (kq0 + kb) * 4;
                se2[(k + 0) * PS + p] = pk2(a.x, b.x);
                se2[(k + 1) * PS + p] = pk2(a.y, b.y);
                se2[(k + 2) * PS + p] = pk2(a.z, b.z);
                se2[(k + 3) * PS + p] = pk2(a.w, b.w);
            }
        }
        __syncthreads();

        unsigned long long acc[4][4];
#pragma unroll
        for (int i = 0; i < 4; i++)
#pragma unroll
            for (int j = 0; j < 4; j++) acc[i][j] = 0ull;

        for (int kk = 0; kk < LD; kk += 4) {
            // x: 4 LDS128, 2 unique addrs/warp (broadcast)
            float4 xv[4];
#pragma unroll
            for (int i = 0; i < 4; i++)
                xv[i] = *(const float4*)(sx + (row0 + i) * XS + kk);
#pragma unroll
            for (int q = 0; q < 4; q++) {
                // e: 4 LDS64 directly into packed operands (16 consecutive
                // float2 per warp -> conflict-free)
                unsigned long long ee[4];
#pragma unroll
                for (int j = 0; j < 4; j++)
                    ee[j] = se2[(kk + q) * PS + col_t + 16 * j];
#pragma unroll
                for (int i = 0; i < 4; i++) {
                    float xq = (q == 0) ? xv[i].x : (q == 1) ? xv[i].y
                             : (q == 2) ? xv[i].z : xv[i].w;
                    unsigned long long xx = pk2(xq, xq);
#pragma unroll
                    for (int j = 0; j < 4; j++)
                        acc[i][j] = fma2(xx, ee[j], acc[i][j]);
                }
            }
        }

        // ---- fold chunk scores into running argmin ----
#pragma unroll
        for (int i = 0; i < 4; i++) {
#pragma unroll
            for (int j = 0; j < 4; j++) {
                float dlo, dhi;
                upk2(acc[i][j], dlo, dhi);
                int n0 = c * NCH + 2 * (col_t + 16 * j);
                int n1 = n0 + 1;
                float s0 = fmaf(-2.f, dlo, g_esq[n0]);
                float s1 = fmaf(-2.f, dhi, g_esq[n1]);
                if (s0 < bestv[i]) { bestv[i] = s0; besti[i] = n0; }
                if (s1 < bestv[i]) { bestv[i] = s1; besti[i] = n1; }
            }
        }
    }

    // ---- cross-thread argmin: orderable key, lowest-index tiebreak ----
    __syncthreads();
    unsigned long long* keys = (unsigned long long*)smem;   // reuse x region
#pragma unroll
    for (int i = 0; i < 4; i++) {
        unsigned u = __float_as_uint(bestv[i]);
        u = (u & 0x80000000u) ? ~u : (u | 0x80000000u);     // monotone map
        keys[(row0 + i) * 16 + col_t] =
            ((unsigned long long)u << 32) | (unsigned)besti[i];
    }
    __syncthreads();
    __shared__ int sidx[MT];
    if (t < MT) {
        unsigned long long m = keys[t * 16];
#pragma unroll
        for (int c2 = 1; c2 < 16; c2++) {
            unsigned long long v = keys[t * 16 + c2];
            if (v < m) m = v;
        }
        sidx[t] = (int)(m & 0xFFFFFFFFull);
    }
    __syncthreads();

    // ---- gather: out[row] = embeddings[idx[row]] ----
    {
        int r = t >> 2, qt = t & 3;
        const float4* src = (const float4*)(emb + (size_t)sidx[r] * LD) + qt * 8;
        float4* dst = (float4*)(out + (base_row + r) * LD) + qt * 8;
#pragma unroll
        for (int q = 0; q < 8; q++) dst[q] = src[q];
    }
}

// ---------------------------------------------------------------------------
extern "C" void kernel_launch(void* const* d_in, const int* in_sizes, int n_in,
                              void* d_out, int out_size) {
    int ii = 0, ei = 1;
    if (n_in > 1 && in_sizes[0] < in_sizes[1]) { ii = 1; ei = 0; }
    const float* inp = (const float*)d_in[ii];
    const float* emb = (const float*)d_in[ei];
    float* out = (float*)d_out;

    int rows = in_sizes[ii] / LD;          // 65536
    int grid = rows / MT;                  // 1024

    esq_kernel<<<1, 256>>>(emb);

    int smem_bytes = MT * XS * (int)sizeof(float)
                   + LD * PS * (int)sizeof(unsigned long long);  // 33792+65536=99328
    static int smem_ok = -1;
    if (smem_ok < 0) {
        cudaError_t e = cudaFuncSetAttribute(
            vq_kernel, cudaFuncAttributeMaxDynamicSharedMemorySize, smem_bytes);
        smem_ok = (e == cudaSuccess) ? 1 : 0;
    }
    vq_kernel<<<grid, 256, smem_bytes>>>(inp, emb, out);
}

// round 5
// speedup vs baseline: 1.1857x; 1.1857x over previous
#include <cuda_runtime.h>
#include <float.h>

#define LD   128   // latent dims
#define NE   256   // num embeddings
#define MT   128   // rows per CTA
#define XS   132   // x smem row stride (floats), float4-aligned
#define PS   128   // e pair-row stride in ULL (128 pairs = 256 cols)

__device__ float g_esq[NE];

// ---------------------------------------------------------------------------
__global__ void esq_kernel(const float* __restrict__ emb) {
    int k = threadIdx.x;            // 0..255
    const float4* row = (const float4*)(emb + (size_t)k * LD);
    float s = 0.f;
#pragma unroll
    for (int q = 0; q < LD / 4; q++) {
        float4 v = row[q];
        s = fmaf(v.x, v.x, s);
        s = fmaf(v.y, v.y, s);
        s = fmaf(v.z, v.z, s);
        s = fmaf(v.w, v.w, s);
    }
    g_esq[k] = s;
}

// ---------------------------------------------------------------------------
__device__ __forceinline__ unsigned long long pk2(float a, float b) {
    unsigned long long r;
    asm("mov.b64 %0, {%1, %2};" : "=l"(r) : "f"(a), "f"(b));
    return r;
}
__device__ __forceinline__ void upk2(unsigned long long v, float& a, float& b) {
    asm("mov.b64 {%0, %1}, %2;" : "=f"(a), "=f"(b) : "l"(v));
}
__device__ __forceinline__ unsigned long long fma2(unsigned long long a,
                                                   unsigned long long b,
                                                   unsigned long long c) {
    unsigned long long d;
    asm("fma.rn.f32x2 %0, %1, %2, %3;" : "=l"(d) : "l"(a), "l"(b), "l"(c));
    return d;
}

extern __shared__ float smem[];
// layout: sx[MT][XS] floats (67584 B) | se2[LD][PS] ULL (131072 B)

// ---------------------------------------------------------------------------
// Fused GEMM + argmin + gather.
// col_t = t&15 owns pairs p = col_t+16j (j=0..7) -> 16 cols; row_t = t>>4
// owns rows row_t*8+i (i=0..7). Software-pipelined: ee double-buffered with
// one-q-step lookahead, xv prefetched at q==3 for the next kk.
// ---------------------------------------------------------------------------
__global__ __launch_bounds__(256, 1)
void vq_kernel(const float* __restrict__ inp, const float* __restrict__ emb,
               float* __restrict__ out) {
    float* sx = smem;
    unsigned long long* se2 = (unsigned long long*)(smem + MT * XS);
    const int t     = threadIdx.x;
    const int col_t = t & 15;
    const int row_t = t >> 4;
    const int row0  = row_t * 8;
    const size_t base_row = (size_t)blockIdx.x * MT;

    // ---- stage x tile [128][128] (coalesced LDG128 -> STS128) ----
    {
        const float4* gin = (const float4*)(inp + base_row * LD);
#pragma unroll
        for (int p = 0; p < 16; p++) {
            int fi  = t + p * 256;          // 0..4095 float4s
            int row = fi >> 5;
            int q   = fi & 31;
            float4 v = gin[fi];
            *(float4*)(sx + row * XS + q * 4) = v;
        }
    }
    // ---- stage e pair-transposed: se2[k][p] = (e[2p][k], e[2p+1][k]) ----
    {
        int p  = t & 127;                   // pair index 0..127
        int k0 = (t >> 7) * 64;             // this thread's k half
        const float4* ra = (const float4*)(emb + (size_t)(2 * p) * LD) + k0 / 4;
        const float4* rb = (const float4*)(emb + (size_t)(2 * p + 1) * LD) + k0 / 4;
#pragma unroll
        for (int kb = 0; kb < 16; kb++) {
            float4 a = ra[kb];
            float4 b = rb[kb];
            int k = k0 + kb * 4;
            se2[(k + 0) * PS + p] = pk2(a.x, b.x);
            se2[(k + 1) * PS + p] = pk2(a.y, b.y);
            se2[(k + 2) * PS + p] = pk2(a.z, b.z);
            se2[(k + 3) * PS + p] = pk2(a.w, b.w);
        }
    }
    __syncthreads();

    unsigned long long acc[8][8];
#pragma unroll
    for (int i = 0; i < 8; i++)
#pragma unroll
        for (int j = 0; j < 8; j++) acc[i][j] = 0ull;

    // ---- pipeline prologue ----
    float4 xv[8];
    unsigned long long ee[2][8];
#pragma unroll
    for (int i = 0; i < 8; i++)
        xv[i] = *(const float4*)(sx + (row0 + i) * XS);
    {
        const unsigned long long* ep = se2 + col_t;
#pragma unroll
        for (int j = 0; j < 8; j++) ee[0][j] = ep[16 * j];
    }

    // ---- main loop: 128 k-steps, fma-bound ----
#pragma unroll 1
    for (int kk = 0; kk < LD; kk += 4) {
#pragma unroll
        for (int q = 0; q < 4; q++) {
            const int cur = q & 1;
            // prefetch next k-step's e pairs (1-step lookahead)
            {
                int kn = (kk + q + 1) & (LD - 1);
                const unsigned long long* ep = se2 + (kn << 7) + col_t;
#pragma unroll
                for (int j = 0; j < 8; j++) ee[cur ^ 1][j] = ep[16 * j];
            }
            // 64 FFMA2 for this k-step
#pragma unroll
            for (int i = 0; i < 8; i++) {
                float xq = (q == 0) ? xv[i].x : (q == 1) ? xv[i].y
                         : (q == 2) ? xv[i].z : xv[i].w;
                unsigned long long xx = pk2(xq, xq);
#pragma unroll
                for (int j = 0; j < 8; j++)
                    acc[i][j] = fma2(xx, ee[cur][j], acc[i][j]);
            }
            // prefetch next kk's x (after last use of current xv)
            if (q == 3) {
                int kx = (kk + 4) & (LD - 1);
#pragma unroll
                for (int i = 0; i < 8; i++)
                    xv[i] = *(const float4*)(sx + (row0 + i) * XS + kx);
            }
        }
    }

    // ---- fold scores into per-thread argmin (ascending n, strict <) ----
    float bestv[8];
    int   besti[8];
#pragma unroll
    for (int i = 0; i < 8; i++) { bestv[i] = FLT_MAX; besti[i] = 0; }
#pragma unroll
    for (int j = 0; j < 8; j++) {
        int n0 = 2 * (col_t + 16 * j);
        float e0 = g_esq[n0], e1 = g_esq[n0 + 1];
#pragma unroll
        for (int i = 0; i < 8; i++) {
            float dlo, dhi;
            upk2(acc[i][j], dlo, dhi);
            float s0 = fmaf(-2.f, dlo, e0);
            float s1 = fmaf(-2.f, dhi, e1);
            if (s0 < bestv[i]) { bestv[i] = s0; besti[i] = n0; }
            if (s1 < bestv[i]) { bestv[i] = s1; besti[i] = n0 + 1; }
        }
    }

    // ---- cross-thread argmin: orderable key, lowest-index tiebreak ----
    __syncthreads();
    unsigned long long* keys = (unsigned long long*)smem;   // reuse x region
#pragma unroll
    for (int i = 0; i < 8; i++) {
        unsigned u = __float_as_uint(bestv[i]);
        u = (u & 0x80000000u) ? ~u : (u | 0x80000000u);     // monotone map
        keys[(row0 + i) * 16 + col_t] =
            ((unsigned long long)u << 32) | (unsigned)besti[i];
    }
    __syncthreads();
    __shared__ int sidx[MT];
    if (t < MT) {
        unsigned long long m = keys[t * 16];
#pragma unroll
        for (int c2 = 1; c2 < 16; c2++) {
            unsigned long long v = keys[t * 16 + c2];
            if (v < m) m = v;
        }
        sidx[t] = (int)(m & 0xFFFFFFFFull);
    }
    __syncthreads();

    // ---- gather: out[row] = embeddings[idx[row]] ----
    {
        int r = t >> 1, half = t & 1;
        const float4* src = (const float4*)(emb + (size_t)sidx[r] * LD) + half * 16;
        float4* dst = (float4*)(out + (base_row + r) * LD) + half * 16;
#pragma unroll
        for (int q = 0; q < 16; q++) dst[q] = src[q];
    }
}

// ---------------------------------------------------------------------------
extern "C" void kernel_launch(void* const* d_in, const int* in_sizes, int n_in,
                              void* d_out, int out_size) {
    int ii = 0, ei = 1;
    if (n_in > 1 && in_sizes[0] < in_sizes[1]) { ii = 1; ei = 0; }
    const float* inp = (const float*)d_in[ii];
    const float* emb = (const float*)d_in[ei];
    float* out = (float*)d_out;

    int rows = in_sizes[ii] / LD;          // 65536
    int grid = rows / MT;                  // 512

    esq_kernel<<<1, 256>>>(emb);

    int smem_bytes = MT * XS * (int)sizeof(float)
                   + LD * PS * (int)sizeof(unsigned long long);  // 198656
    static int smem_ok = -1;
    if (smem_ok < 0) {
        cudaError_t e = cudaFuncSetAttribute(
            vq_kernel, cudaFuncAttributeMaxDynamicSharedMemorySize, smem_bytes);
        smem_ok = (e == cudaSuccess) ? 1 : 0;
    }
    vq_kernel<<<grid, 256, smem_bytes>>>(inp, emb, out);
}